// round 13
// baseline (speedup 1.0000x reference)
#include <cuda_runtime.h>
#include <cuda_bf16.h>
#include <cuda_fp16.h>
#include <cstdint>

// Problem constants (fixed by the dataset)
static constexpr int NN    = 100000;   // nodes
static constexpr int EE    = 3200000;  // edges
static constexpr int DIN   = 128;
static constexpr int HID   = 16;
static constexpr int DOUT  = 12;
static constexpr int NMID  = 11;

static constexpr int NGRP  = (NN + 7) / 8;           // 12500 warp-groups of 8 nodes
static constexpr int ECAP  = EE + 64 * NGRP;         // transposed slots incl. padding
static constexpr int PGRID = 444;                    // 3 blocks/SM on 148 SMs (resident)

// ---------------- scratch (device globals; referenced only in device code) --
__device__ int                g_is64;
__device__ unsigned long long g_pk[NN];      // hi32 = count, lo32 = sum(w)*2^24
__device__ float  g_dis[NN];                 // rsqrt(deg)
__device__ float  g_selfw[NN];               // 1/deg
__device__ int    g_cnt[NN];                 // fill counters for scatter
__device__ int    g_dhist[256];              // degree histogram (clamped at 255)
__device__ int    g_doff[256];               // degree bucket offsets
__device__ int2   g_snode[NN];               // sorted: {node, selfw_bits}
__device__ int    g_sdeg[NN];                // sorted: edge count
__device__ int    g_sortpos[NN];             // node -> sorted position
__device__ int    g_gdeg[NGRP];              // per-group max degree
__device__ int    g_goff[NGRP + 1];          // group slot offsets (8*sum(maxdeg))
__device__ float2 g_edge2[ECAP];             // slot goff[g]+k*8+p = edge k of member p
__device__ uint2  g_hb0[NN * 4];             // fp16 features: 16 halves = 4x uint2/node
__device__ uint2  g_hb1[NN * 4];
__device__ unsigned g_barcnt;                // grid barrier (self-resetting)
__device__ unsigned g_bargen;

// ---------------- fp16 helpers ----------------------------------------------
__device__ __forceinline__ void cvt4(uint2 v, float* f) {
    __half2 h0 = *reinterpret_cast<__half2*>(&v.x);
    __half2 h1 = *reinterpret_cast<__half2*>(&v.y);
    float2 a0 = __half22float2(h0);
    float2 a1 = __half22float2(h1);
    f[0] = a0.x; f[1] = a0.y; f[2] = a1.x; f[3] = a1.y;
}
__device__ __forceinline__ uint2 pack4(const float* o) {
    uint2 r;
    __half2 p0 = __floats2half2_rn(o[0], o[1]);
    __half2 p1 = __floats2half2_rn(o[2], o[3]);
    r.x = *reinterpret_cast<unsigned*>(&p0);
    r.y = *reinterpret_cast<unsigned*>(&p1);
    return r;
}

__device__ __forceinline__ int eidx(const void* ei, bool is64, long long i) {
    if (is64) return (int)((const long long*)ei)[i];
    return ((const int*)ei)[i];
}

// ---------------- software grid barrier --------------------------------------
// Classic count+generation barrier. Self-resetting (count returns to 0 each
// use) so repeated graph replays see identical initial state. All blocks are
// guaranteed co-resident (grid=444 <= 3/SM * 148 via __launch_bounds__).
__device__ __forceinline__ void gbar(unsigned nb) {
    __threadfence();                       // release this block's writes
    __syncthreads();
    if (threadIdx.x == 0) {
        unsigned gen = atomicAdd(&g_bargen, 0u);   // read gen BEFORE arriving
        unsigned a   = atomicAdd(&g_barcnt, 1u);
        if (a == nb - 1) {
            atomicExch(&g_barcnt, 0u);     // reset for next use
            __threadfence();
            atomicAdd(&g_bargen, 1u);      // release
        } else {
            while (atomicAdd(&g_bargen, 0u) == gen) __nanosleep(100);
        }
    }
    __syncthreads();
    __threadfence();                       // acquire other blocks' writes
}

// ---------------- preprocessing ---------------------------------------------
__global__ void k_init(const unsigned int* p) {
    int i = blockIdx.x * blockDim.x + threadIdx.x;
    if (i < NN) { g_pk[i] = 0ull; g_cnt[i] = 0; }
    if (blockIdx.x == 0) {
        __shared__ unsigned int s_or;
        if (threadIdx.x == 0) s_or = 0u;
        __syncthreads();
        unsigned int acc = 0;
        for (int j = threadIdx.x; j < 1024; j += blockDim.x)
            acc |= p[2 * j + 1];
        if (acc) atomicOr(&s_or, acc);
        __syncthreads();
        if (threadIdx.x == 0) g_is64 = (s_or == 0u) ? 1 : 0;
        if (threadIdx.x < 256) g_dhist[threadIdx.x] = 0;
    }
}

// one packed 64-bit atomic per edge: count in hi32, fixed-point weight in lo32
__global__ void k_degcnt(const void* ei, const float* __restrict__ w) {
    bool is64 = (g_is64 != 0);
    for (int e = blockIdx.x * blockDim.x + threadIdx.x; e < EE;
         e += gridDim.x * blockDim.x) {
        int c = eidx(ei, is64, (long long)EE + e);
        unsigned int fx = (unsigned int)__float2uint_rn(w[e] * 16777216.f);
        atomicAdd(&g_pk[c], (1ull << 32) | (unsigned long long)fx);
    }
}

__global__ void k_normhist() {
    __shared__ int sh[256];
    int tid = threadIdx.x;
    sh[tid] = 0;
    __syncthreads();
    int i = blockIdx.x * blockDim.x + tid;
    if (i < NN) {
        unsigned long long pk = g_pk[i];
        int v = (int)(pk >> 32);
        float d = (float)(unsigned int)(pk & 0xffffffffu) * (1.f / 16777216.f) + 1.0f;
        g_dis[i]   = rsqrtf(d);
        g_selfw[i] = 1.0f / d;
        atomicAdd(&sh[v < 255 ? v : 255], 1);
    }
    __syncthreads();
    if (sh[tid]) atomicAdd(&g_dhist[tid], sh[tid]);
}

__global__ void k_scanh() {
    __shared__ int s[256];
    int t = threadIdx.x;
    int v = g_dhist[t];
    s[t] = v;
    __syncthreads();
    for (int off = 1; off < 256; off <<= 1) {
        int x = (t >= off) ? s[t - off] : 0;
        __syncthreads();
        s[t] += x;
        __syncthreads();
    }
    g_doff[t] = s[t] - v;        // exclusive bucket offsets
}

__global__ void k_sort() {
    __shared__ int sh[256];
    __shared__ int base[256];
    int tid = threadIdx.x;
    if (tid < 256) sh[tid] = 0;
    __syncthreads();
    int i = blockIdx.x * 1024 + tid;
    bool act = (i < NN);
    int c = 0, d = 0, inblk = 0;
    if (act) {
        c = (int)(g_pk[i] >> 32);
        d = c < 255 ? c : 255;
        inblk = atomicAdd(&sh[d], 1);
    }
    __syncthreads();
    if (tid < 256) base[tid] = sh[tid] ? atomicAdd(&g_doff[tid], sh[tid]) : 0;
    __syncthreads();
    if (act) {
        int pos = base[d] + inblk;
        g_snode[pos]  = make_int2(i, __float_as_int(g_selfw[i]));
        g_sdeg[pos]   = c;
        g_sortpos[i]  = pos;
    }
}

__global__ void k_gmax() {
    int g = blockIdx.x * blockDim.x + threadIdx.x;
    if (g >= NGRP) return;
    int m = 0;
    #pragma unroll
    for (int j = 0; j < 8; j++) {
        int pos = g * 8 + j;
        if (pos < NN) { int c = g_sdeg[pos]; m = c > m ? c : m; }
    }
    g_gdeg[g] = m;
}

__global__ void k_gscan() {
    __shared__ int s[1024];
    __shared__ int carry;
    int tid = threadIdx.x;
    if (tid == 0) { carry = 0; g_goff[0] = 0; }
    __syncthreads();
    for (int c0 = 0; c0 < NGRP; c0 += 1024) {
        int g = c0 + tid;
        int v = (g < NGRP) ? 8 * g_gdeg[g] : 0;
        s[tid] = v;
        __syncthreads();
        for (int off = 1; off < 1024; off <<= 1) {
            int x = (tid >= off) ? s[tid - off] : 0;
            __syncthreads();
            s[tid] += x;
            __syncthreads();
        }
        if (g < NGRP) g_goff[g + 1] = carry + s[tid];
        __syncthreads();
        if (tid == 1023) carry += s[1023];
        __syncthreads();
    }
}

__global__ void k_pad() {
    int pos = blockIdx.x * blockDim.x + threadIdx.x;
    if (pos >= NN) return;
    int g = pos >> 3, lane = pos & 7;
    int c = g_sdeg[pos];
    int base = g_goff[g];
    int K = (g_goff[g + 1] - base) >> 3;
    for (int k = c; k < K; k++)
        g_edge2[base + k * 8 + lane] = make_float2(__int_as_float(0), 0.f);
}

__global__ void k_scatter(const void* ei, const float* __restrict__ w) {
    bool is64 = (g_is64 != 0);
    for (int e = blockIdx.x * blockDim.x + threadIdx.x; e < EE;
         e += gridDim.x * blockDim.x) {
        int r = eidx(ei, is64, e);
        int c = eidx(ei, is64, (long long)EE + e);
        int k    = atomicAdd(&g_cnt[c], 1);
        int sp   = g_sortpos[c];
        int slot = g_goff[sp >> 3] + k * 8 + (sp & 7);
        g_edge2[slot] = make_float2(__int_as_float(r), g_dis[r] * w[e] * g_dis[c]);
    }
}

// ---------------- layer 0 GEMM: x[N,128] @ W0[128,16] -> g_hb0 (fp16) -------
__global__ void k_gemm0(const float* __restrict__ x, const float* __restrict__ W0) {
    __shared__ float Ws[DIN * HID];   // 8 KB
    __shared__ float xs[16 * DIN];    // 8 KB
    int tid = threadIdx.x;
    for (int i = tid; i < DIN * HID; i += 256) Ws[i] = W0[i];
    int n0 = blockIdx.x * 16;
    for (int i = tid; i < 16 * DIN; i += 256) {
        int nn = n0 + i / DIN;
        xs[i] = (nn < NN) ? x[(size_t)nn * DIN + (i % DIN)] : 0.f;
    }
    __syncthreads();
    int ln = tid >> 4, f = tid & 15;
    int n = n0 + ln;
    if (n < NN) {
        float acc = 0.f;
        #pragma unroll
        for (int k = 0; k < DIN; k++) acc += xs[ln * DIN + k] * Ws[k * HID + f];
        reinterpret_cast<__half*>(g_hb0)[n * HID + f] = __float2half_rn(acc);
    }
}

// ---------------- agg mainloop core -----------------------------------------
// 4 lanes per node (lane owns 4 feats as uint2 of halves); 8 nodes per warp.
// Unroll 8 with software-pipelined meta prefetch.
__device__ __forceinline__ void agg_core(const uint2* __restrict__ tq,
                                         const float2* __restrict__ ep,
                                         int K, int l4, float* acc) {
    int k = 0;
    if (K >= 8) {
        float2 e[8];
        #pragma unroll
        for (int j = 0; j < 8; j++) e[j] = ep[j * 8];
        for (; k + 16 <= K; k += 8) {
            uint2 v[8];
            float w8[8];
            #pragma unroll
            for (int j = 0; j < 8; j++) {
                v[j]  = tq[__float_as_int(e[j].x) * 4 + l4];
                w8[j] = e[j].y;
            }
            #pragma unroll
            for (int j = 0; j < 8; j++) e[j] = ep[(k + 8 + j) * 8];  // prefetch
            #pragma unroll
            for (int j = 0; j < 8; j++) {
                float f[4];
                cvt4(v[j], f);
                acc[0] += w8[j] * f[0]; acc[1] += w8[j] * f[1];
                acc[2] += w8[j] * f[2]; acc[3] += w8[j] * f[3];
            }
        }
        {   // last full batch (edges k..k+7 already in e)
            uint2 v[8];
            float w8[8];
            #pragma unroll
            for (int j = 0; j < 8; j++) {
                v[j]  = tq[__float_as_int(e[j].x) * 4 + l4];
                w8[j] = e[j].y;
            }
            #pragma unroll
            for (int j = 0; j < 8; j++) {
                float f[4];
                cvt4(v[j], f);
                acc[0] += w8[j] * f[0]; acc[1] += w8[j] * f[1];
                acc[2] += w8[j] * f[2]; acc[3] += w8[j] * f[3];
            }
            k += 8;
        }
    }
    for (; k < K; k++) {
        float2 ed = ep[k * 8];
        float f[4];
        cvt4(tq[__float_as_int(ed.x) * 4 + l4], f);
        acc[0] += ed.y * f[0]; acc[1] += ed.y * f[1];
        acc[2] += ed.y * f[2]; acc[3] += ed.y * f[3];
    }
}

// ---------------- persistent kernel: all 12 fused layers + final agg --------
// Grid = PGRID (3 blocks/SM, guaranteed co-resident by __launch_bounds__).
// Weights/biases cached in shared once; software grid barrier between layers.
__global__ void __launch_bounds__(256, 3) k_layers(
    const float* __restrict__ b0,   const float* __restrict__ Wmid,
    const float* __restrict__ bmid, const float* __restrict__ Wlast,
    const float* __restrict__ blast, float* __restrict__ outp) {
    __shared__ float Ws[12 * 256];   // W for fused layers 0..11 (layer 11 padded)
    __shared__ float Bs[13 * 16];    // biases: b0, bmid[0..10], blast (padded)

    int tid = threadIdx.x;
    for (int i = tid; i < 11 * 256; i += 256) Ws[i] = Wmid[i];
    for (int i = tid; i < 256; i += 256) {
        int k = i >> 4, fo = i & 15;
        Ws[11 * 256 + i] = (fo < DOUT) ? Wlast[k * DOUT + fo] : 0.f;
    }
    if (tid < 16)  Bs[tid] = b0[tid];
    for (int i = tid; i < 11 * 16; i += 256) Bs[16 + i] = bmid[i];
    if (tid < 16)  Bs[12 * 16 + tid] = (tid < DOUT) ? blast[tid] : 0.f;
    __syncthreads();

    const unsigned nb = gridDim.x;
    const int nwarp = (int)nb * 8;
    const int gw0  = (blockIdx.x * 256 + tid) >> 5;   // global warp id
    const int lane = tid & 31;
    const int p  = lane >> 2;
    const int l4 = lane & 3;

    // ---- 12 fused agg(+bias+relu)+GEMM layers ----
    #pragma unroll 1
    for (int l = 0; l < 12; l++) {
        const uint2* __restrict__ tq  = (l & 1) ? g_hb1 : g_hb0;
        uint2*       __restrict__ dst = (l & 1) ? g_hb0 : g_hb1;
        const float* Wl = &Ws[l * 256];
        const float* bl = &Bs[l * 16];
        float4 bv = *(const float4*)(bl + l4 * 4);

        for (int g = gw0; g < NGRP; g += nwarp) {
            int2  sn = g_snode[g * 8 + p];
            int   n  = sn.x;
            float sw = __int_as_float(sn.y);
            int base = g_goff[g];
            int K    = (g_goff[g + 1] - base) >> 3;

            float acc[4], f0[4];
            cvt4(tq[n * 4 + l4], f0);
            #pragma unroll
            for (int j = 0; j < 4; j++) acc[j] = sw * f0[j];

            agg_core(tq, g_edge2 + base + p, K, l4, acc);

            float h[4];
            h[0] = fmaxf(acc[0] + bv.x, 0.f);
            h[1] = fmaxf(acc[1] + bv.y, 0.f);
            h[2] = fmaxf(acc[2] + bv.z, 0.f);
            h[3] = fmaxf(acc[3] + bv.w, 0.f);

            // reconstruct full 16-feat row within the 4-lane group
            float hrow[16];
            #pragma unroll
            for (int q = 0; q < 16; q++)
                hrow[q] = __shfl_sync(0xffffffffu, h[q & 3], q >> 2, 4);

            float o[4] = {0, 0, 0, 0};
            #pragma unroll
            for (int kk = 0; kk < HID; kk++) {
                float hk = hrow[kk];
                const float* wr = &Wl[kk * 16 + l4 * 4];
                o[0] += hk * wr[0]; o[1] += hk * wr[1];
                o[2] += hk * wr[2]; o[3] += hk * wr[3];
            }
            dst[n * 4 + l4] = pack4(o);
        }
        gbar(nb);
    }

    // ---- final aggregation (F=12) into harness out (fp32) ----
    {
        const uint2* __restrict__ tq = g_hb0;    // layer 11 wrote hb0
        float4 bv = *(const float4*)(&Bs[12 * 16] + l4 * 4);
        for (int g = gw0; g < NGRP; g += nwarp) {
            int2  sn = g_snode[g * 8 + p];
            int   n  = sn.x;
            float sw = __int_as_float(sn.y);
            int base = g_goff[g];
            int K    = (g_goff[g + 1] - base) >> 3;

            float acc[4], f0[4];
            cvt4(tq[n * 4 + l4], f0);
            #pragma unroll
            for (int j = 0; j < 4; j++) acc[j] = sw * f0[j];

            agg_core(tq, g_edge2 + base + p, K, l4, acc);

            if (l4 < 3) {   // only feats 0..11 exist; rows are 48B
                float4 r;
                r.x = fmaxf(acc[0] + bv.x, 0.f);
                r.y = fmaxf(acc[1] + bv.y, 0.f);
                r.z = fmaxf(acc[2] + bv.z, 0.f);
                r.w = fmaxf(acc[3] + bv.w, 0.f);
                *(float4*)(outp + (size_t)n * DOUT + l4 * 4) = r;
            }
        }
    }
}

// ---------------- launch ----------------------------------------------------
extern "C" void kernel_launch(void* const* d_in, const int* in_sizes, int n_in,
                              void* d_out, int out_size) {
    const float* x     = (const float*)d_in[0];
    const void*  ei    = d_in[1];
    const float* w     = (const float*)d_in[2];
    const float* W0    = (const float*)d_in[3];
    const float* b0    = (const float*)d_in[4];
    const float* Wmid  = (const float*)d_in[5];
    const float* bmid  = (const float*)d_in[6];
    const float* Wlast = (const float*)d_in[7];
    const float* blast = (const float*)d_in[8];
    float* out = (float*)d_out;

    const int TB = 256;
    const int nblkN = (NN + TB - 1) / TB;
    const int nblkE = 2048;

    // --- preprocessing ---
    k_init<<<nblkN, TB>>>((const unsigned int*)ei);
    k_degcnt<<<nblkE, TB>>>(ei, w);
    k_normhist<<<nblkN, TB>>>();
    k_scanh<<<1, 256>>>();
    k_sort<<<(NN + 1023) / 1024, 1024>>>();
    k_gmax<<<(NGRP + TB - 1) / TB, TB>>>();
    k_gscan<<<1, 1024>>>();
    k_pad<<<nblkN, TB>>>();
    k_scatter<<<nblkE, TB>>>(ei, w);

    // --- layer 0 GEMM -> hb0 (fp16) ---
    k_gemm0<<<(NN + 15) / 16, 256>>>(x, W0);

    // --- all 12 fused layers + final agg in ONE persistent kernel ---
    k_layers<<<PGRID, TB>>>(b0, Wmid, bmid, Wlast, blast, out);
}